// round 9
// baseline (speedup 1.0000x reference)
#include <cuda_runtime.h>
#include <cuda_fp16.h>

#define N_NODES 100000
#define N_EDGES 20000
#define NNZ     1600000
#define ESTRIDE 256   // max tracked nodes per edge (deg ~ mean 80, sd 9)
#define NSTRIDE 64    // max tracked edges per node (mean 16, sd 4)

// ---------------- scratch (device globals; zero-initialized at module load) ----------
// RULE: each global is accessed EITHER only via host-passed args OR only via device
// symbols — never both (host and device resolutions differ on this toolchain).
__device__ __half          g_x16[(size_t)N_NODES * 300];   // fp16 x copy (host-arg only)
__device__ float           g_eagg[(size_t)N_EDGES * 300];  // edge-agg feats (host-arg only)
__device__ __half          g_ew[(size_t)N_EDGES * 256];    // edge feats after W (host-arg only)
__device__ __half          g_h[(size_t)N_NODES * 256];     // node activations (host-arg only)
__device__ int             g_ecursor[N_EDGES];             // device-symbol only
__device__ int             g_ncursor[N_NODES];             // device-symbol only
__device__ int             g_ebkt[(size_t)N_EDGES * ESTRIDE];   // device-symbol only
__device__ unsigned short  g_nbkt[(size_t)N_NODES * NSTRIDE];   // device-symbol only
__device__ float           g_logits[N_NODES];              // device-symbol only
__device__ float           g_partmax[12500];               // device-symbol only
__device__ float           g_gmax;                         // device-symbol only
__device__ float           g_acc[129];                     // device-symbol only

// unpack 4 fp16 (as uint2) -> float4 accumulate; pack float4 -> 4 fp16
static __device__ __forceinline__ void acc_h4(float4& acc, uint2 raw) {
    float2 f0 = __half22float2(*reinterpret_cast<__half2*>(&raw.x));
    float2 f1 = __half22float2(*reinterpret_cast<__half2*>(&raw.y));
    acc.x += f0.x; acc.y += f0.y; acc.z += f1.x; acc.w += f1.y;
}
static __device__ __forceinline__ uint2 pack_h4(float4 o) {
    __half2 v0 = __floats2half2_rn(o.x, o.y);
    __half2 v1 = __floats2half2_rn(o.z, o.w);
    uint2 pk;
    pk.x = *reinterpret_cast<unsigned*>(&v0);
    pk.y = *reinterpret_cast<unsigned*>(&v1);
    return pk;
}

// ---------------- bucket CSR build (cursors must be 0 on entry) ----------------------
__global__ void build_kernel(const int* __restrict__ nidx, const int* __restrict__ eidx) {
    int i = blockIdx.x * blockDim.x + threadIdx.x;
    int stride = gridDim.x * blockDim.x;
    for (int j = i; j < NNZ; j += stride) {
        int n = nidx[j];
        int e = eidx[j];
        int p = atomicAdd(&g_ecursor[e], 1);
        if (p < ESTRIDE) g_ebkt[(size_t)e * ESTRIDE + p] = n;
        int q = atomicAdd(&g_ncursor[n], 1);
        if (q < NSTRIDE) g_nbkt[(size_t)n * NSTRIDE + q] = (unsigned short)e;
    }
}

// ---------------- x (fp32) -> dst (fp16), vectorized; dst passed from host -----------
__global__ void x2h_kernel(const float* __restrict__ x, __half* __restrict__ dst) {
    const int total4 = N_NODES * 300 / 4;   // 7.5M float4 groups
    int i = blockIdx.x * blockDim.x + threadIdx.x;
    int stride = gridDim.x * blockDim.x;
    for (int j = i; j < total4; j += stride) {
        float4 v = ((const float4*)x)[j];
        ((uint2*)dst)[j] = pack_h4(v);
    }
}

// ---------------- edge aggregation from fp16 source ----------------------------------
// warp per (edge, 128-feature chunk); 8 independent 8B gathers in flight.
template <int F, int CHUNKS>
__global__ __launch_bounds__(256) void agg_edge_f16(const __half* __restrict__ src,
                                                    float* __restrict__ dst) {
    int w = (blockIdx.x * blockDim.x + threadIdx.x) >> 5;
    int lane = threadIdx.x & 31;
    int row = w / CHUNKS;
    int ch  = w % CHUNKS;
    if (row >= N_EDGES) return;

    const int* __restrict__ lst = g_ebkt + (size_t)row * ESTRIDE;
    int tc  = g_ecursor[row];
    int cnt = tc < ESTRIDE ? tc : ESTRIDE;

    int colbase = ch * 128 + lane * 4;
    const bool active = colbase < F;               // partial last chunk for F=300
    const __half* __restrict__ sp = src + colbase;

    float4 acc = make_float4(0.f, 0.f, 0.f, 0.f);
    int i = 0;
    for (; i + 8 <= cnt; i += 8) {
        int idxreg = 0;
        if (lane < 8) idxreg = lst[i + lane];
        int ns[8];
#pragma unroll
        for (int k = 0; k < 8; k++) ns[k] = __shfl_sync(0xffffffffu, idxreg, k);
        uint2 raw[8];
#pragma unroll
        for (int k = 0; k < 8; k++) {
            raw[k] = make_uint2(0u, 0u);
            if (active) raw[k] = *(const uint2*)(sp + (size_t)ns[k] * F);
        }
#pragma unroll
        for (int k = 0; k < 8; k++) acc_h4(acc, raw[k]);
    }
    for (; i < cnt; i++) {
        if (active) {
            uint2 raw = *(const uint2*)(sp + (size_t)lst[i] * F);
            acc_h4(acc, raw);
        }
    }
    if (!active) return;
    float inv = (tc > 0) ? 1.0f / (float)tc : 0.0f;
    float4 o = make_float4(acc.x * inv, acc.y * inv, acc.z * inv, acc.w * inv);
    *(float4*)(dst + (size_t)row * F + colbase) = o;
}

// ---------------- node aggregation: fp16 ew -> fp16 h, +bias, optional lrelu ---------
template <int F, int CHUNKS, bool LRELU>
__global__ __launch_bounds__(256) void agg_node_f16(const __half* __restrict__ src,
                                                    __half* __restrict__ dst,
                                                    const float* __restrict__ bias) {
    int w = (blockIdx.x * blockDim.x + threadIdx.x) >> 5;
    int lane = threadIdx.x & 31;
    int row = w / CHUNKS;
    int ch  = w % CHUNKS;
    if (row >= N_NODES) return;

    const unsigned short* __restrict__ lst = g_nbkt + (size_t)row * NSTRIDE;
    int tc  = g_ncursor[row];
    int cnt = tc < NSTRIDE ? tc : NSTRIDE;

    int colbase = ch * 128 + lane * 4;
    const __half* __restrict__ sp = src + colbase;

    float4 acc = make_float4(0.f, 0.f, 0.f, 0.f);
    int i = 0;
    for (; i + 8 <= cnt; i += 8) {
        int idxreg = 0;
        if (lane < 8) idxreg = (int)lst[i + lane];
        int ns[8];
#pragma unroll
        for (int k = 0; k < 8; k++) ns[k] = __shfl_sync(0xffffffffu, idxreg, k);
        uint2 raw[8];
#pragma unroll
        for (int k = 0; k < 8; k++) raw[k] = *(const uint2*)(sp + (size_t)ns[k] * F);
#pragma unroll
        for (int k = 0; k < 8; k++) acc_h4(acc, raw[k]);
    }
    for (; i < cnt; i++) {
        uint2 raw = *(const uint2*)(sp + (size_t)lst[i] * F);
        acc_h4(acc, raw);
    }
    float inv = (tc > 0) ? 1.0f / (float)tc : 0.0f;
    float4 bb = *(const float4*)(bias + colbase);
    float4 o;
    o.x = acc.x * inv + bb.x;
    o.y = acc.y * inv + bb.y;
    o.z = acc.z * inv + bb.z;
    o.w = acc.w * inv + bb.w;
    if (LRELU) {
        o.x = (o.x > 0.f) ? o.x : 0.01f * o.x;
        o.y = (o.y > 0.f) ? o.y : 0.01f * o.y;
        o.z = (o.z > 0.f) ? o.z : 0.01f * o.z;
        o.w = (o.w > 0.f) ? o.w : 0.01f * o.w;
    }
    *(uint2*)(dst + (size_t)row * F + colbase) = pack_h4(o);
}

// ---------------- fp32 SGEMM, fp16 output: C[M,N] = A[M,K] @ B[K,N] ------------------
__global__ __launch_bounds__(256) void sgemm_kernel(const float* __restrict__ A,
                                                    const float* __restrict__ B,
                                                    __half* __restrict__ C,
                                                    int M, int K, int N) {
    __shared__ float As[8][136];
    __shared__ float Bs[8][64];
    const int tid = threadIdx.x;
    const int bm = blockIdx.x * 128;
    const int bn = blockIdx.y * 64;
    const int a_row = tid >> 1;
    const int a_col = (tid & 1) * 4;
    const int b_row = tid >> 5;
    const int b_col = (tid & 31) * 2;
    const int ty = tid >> 4;
    const int tx = tid & 15;
    float acc[8][4];
#pragma unroll
    for (int i = 0; i < 8; i++)
#pragma unroll
        for (int j = 0; j < 4; j++) acc[i][j] = 0.f;

    const bool arow_ok = (bm + a_row) < M;
    const float* Ab = A + (size_t)(bm + a_row) * K;

    for (int kt = 0; kt < K; kt += 8) {
#pragma unroll
        for (int j = 0; j < 4; j++) {
            int k = kt + a_col + j;
            As[a_col + j][a_row] = (arow_ok && k < K) ? Ab[k] : 0.f;
        }
        {
            int k = kt + b_row;
            float2 bv = make_float2(0.f, 0.f);
            if (k < K) bv = *(const float2*)(B + (size_t)k * N + bn + b_col);
            *(float2*)&Bs[b_row][b_col] = bv;
        }
        __syncthreads();
#pragma unroll
        for (int k = 0; k < 8; k++) {
            float4 a0 = *(const float4*)&As[k][ty * 8];
            float4 a1 = *(const float4*)&As[k][ty * 8 + 4];
            float4 bv = *(const float4*)&Bs[k][tx * 4];
            float a[8] = {a0.x, a0.y, a0.z, a0.w, a1.x, a1.y, a1.z, a1.w};
            float b[4] = {bv.x, bv.y, bv.z, bv.w};
#pragma unroll
            for (int i = 0; i < 8; i++)
#pragma unroll
                for (int j = 0; j < 4; j++) acc[i][j] += a[i] * b[j];
        }
        __syncthreads();
    }
#pragma unroll
    for (int i = 0; i < 8; i++) {
        int r = bm + ty * 8 + i;
        if (r < M) {
            float4 o = make_float4(acc[i][0], acc[i][1], acc[i][2], acc[i][3]);
            *(uint2*)(C + (size_t)r * N + bn + tx * 4) = pack_h4(o);
        }
    }
}

// ---------------- attention epilogue (h is fp16, stride 128) -------------------------
// Also zeroes bucket cursors for the next replay.
__global__ void logits_kernel(const __half* __restrict__ h,
                              const float* __restrict__ aw, const float* __restrict__ ab) {
    __shared__ float smax[8];
    int gidx = blockIdx.x * blockDim.x + threadIdx.x;
    int gstride = gridDim.x * blockDim.x;
    for (int j = gidx; j < N_EDGES; j += gstride) g_ecursor[j] = 0;
    for (int j = gidx; j < N_NODES; j += gstride) g_ncursor[j] = 0;

    int w = gidx >> 5;
    int lane = threadIdx.x & 31;
    float lg = -1e30f;
    if (w < N_NODES) {
        uint2 raw = *(const uint2*)(h + (size_t)w * 128 + lane * 4);
        float2 f0 = __half22float2(*reinterpret_cast<__half2*>(&raw.x));
        float2 f1 = __half22float2(*reinterpret_cast<__half2*>(&raw.y));
        float4 wv = ((const float4*)aw)[lane];
        float d = f0.x * wv.x + f0.y * wv.y + f1.x * wv.z + f1.y * wv.w;
#pragma unroll
        for (int off = 16; off > 0; off >>= 1) d += __shfl_xor_sync(0xffffffffu, d, off);
        d += ab[0];
        if (lane == 0) g_logits[w] = d;
        lg = d;
    }
    int wl = threadIdx.x >> 5;
    if (lane == 0) smax[wl] = lg;
    __syncthreads();
    if (threadIdx.x == 0) {
        float m = smax[0];
#pragma unroll
        for (int j = 1; j < 8; j++) m = fmaxf(m, smax[j]);
        g_partmax[blockIdx.x] = m;
    }
}

// global max of logits; also zeroes g_acc for the upcoming accum
__global__ void maxred_kernel(int nparts) {
    __shared__ float sm[32];
    if (threadIdx.x < 129) g_acc[threadIdx.x] = 0.0f;
    float m = -1e30f;
    for (int i = threadIdx.x; i < nparts; i += 1024) m = fmaxf(m, g_partmax[i]);
#pragma unroll
    for (int off = 16; off > 0; off >>= 1) m = fmaxf(m, __shfl_xor_sync(0xffffffffu, m, off));
    if ((threadIdx.x & 31) == 0) sm[threadIdx.x >> 5] = m;
    __syncthreads();
    if (threadIdx.x < 32) {
        float v = sm[threadIdx.x];
#pragma unroll
        for (int off = 16; off > 0; off >>= 1) v = fmaxf(v, __shfl_xor_sync(0xffffffffu, v, off));
        if (threadIdx.x == 0) g_gmax = v;
    }
}

__global__ void accum_kernel(const __half* __restrict__ h) {
    int t = threadIdx.x;           // 0..127 feature column
    float gmax = g_gmax;
    int per = (N_NODES + gridDim.x - 1) / gridDim.x;
    int n0 = blockIdx.x * per;
    int n1 = n0 + per;
    if (n1 > N_NODES) n1 = N_NODES;
    float acc = 0.f, z = 0.f;
    for (int n = n0; n < n1; n++) {
        float wgt = expf(g_logits[n] - gmax);
        acc += wgt * __half2float(h[(size_t)n * 128 + t]);
        z += wgt;
    }
    atomicAdd(&g_acc[t], acc);
    if (t == 0) atomicAdd(&g_acc[128], z);
}

__global__ void finalize_kernel(float* __restrict__ out) {
    int t = threadIdx.x;
    out[t] = g_acc[t] / g_acc[128];
}

// ---------------- launch -------------------------------------------------------------
extern "C" void kernel_launch(void* const* d_in, const int* in_sizes, int n_in,
                              void* d_out, int out_size) {
    const float* x       = (const float*)d_in[0];          // [100000, 300]
    const int*   nidx    = (const int*)d_in[1];            // hyper_edge_index[0]
    const int*   eidx    = ((const int*)d_in[1]) + NNZ;    // hyper_edge_index[1]
    const float* W1      = (const float*)d_in[2];          // [300,256]
    const float* b1      = (const float*)d_in[3];
    const float* W2      = (const float*)d_in[4];          // [256,256]
    const float* b2      = (const float*)d_in[5];
    const float* W3      = (const float*)d_in[6];          // [256,128]
    const float* b3      = (const float*)d_in[7];
    const float* attn_W  = (const float*)d_in[8];          // [128,1]
    const float* attn_b  = (const float*)d_in[9];          // [1]
    float* out = (float*)d_out;                            // [128]

    // slots 1-4; ncu -s5 -c1 captures slot 4 = sgemm1 (first unprofiled heavy kernel)
    build_kernel<<<4096, 256>>>(nidx, eidx);
    x2h_kernel<<<8192, 256>>>(x, g_x16);                   // dst passed from host (consistent)
    agg_edge_f16<300, 3><<<7500, 256>>>(g_x16, g_eagg);
    sgemm_kernel<<<dim3(157, 4), 256>>>(g_eagg, W1, g_ew, N_EDGES, 300, 256);   // <- capture
    agg_node_f16<256, 2, true><<<25000, 256>>>(g_ew, g_h, b1);

    // Layer 2
    agg_edge_f16<256, 2><<<5000, 256>>>(g_h, g_eagg);
    sgemm_kernel<<<dim3(157, 4), 256>>>(g_eagg, W2, g_ew, N_EDGES, 256, 256);
    agg_node_f16<256, 2, true><<<25000, 256>>>(g_ew, g_h, b2);

    // Layer 3 (no activation)
    agg_edge_f16<256, 2><<<5000, 256>>>(g_h, g_eagg);
    sgemm_kernel<<<dim3(157, 2), 256>>>(g_eagg, W3, g_ew, N_EDGES, 256, 128);
    agg_node_f16<128, 1, false><<<12500, 256>>>(g_ew, g_h, b3);

    // Attention pooling (softmax over nodes, weighted sum -> [128])
    logits_kernel<<<12500, 256>>>(g_h, attn_W, attn_b);
    maxred_kernel<<<1, 1024>>>(12500);
    accum_kernel<<<512, 128>>>(g_h);
    finalize_kernel<<<1, 128>>>(out);
}

// round 10
// speedup vs baseline: 1.4484x; 1.4484x over previous
#include <cuda_runtime.h>
#include <cuda_fp16.h>

#define N_NODES 100000
#define N_EDGES 20000
#define NNZ     1600000
#define LDA1    304     // padded fp16 row stride for K=300 (16B-aligned rows; pad stays 0)

// ---------------- scratch (device globals; zero-initialized at module load) ----------
// RULE: each array is accessed EITHER only via host-passed args OR only via device
// symbols — never both (host/device symbol resolutions differ on this toolchain).
__device__ __half          g_eagg[(size_t)N_EDGES * LDA1]; // edge-agg feats fp16 (host-arg only)
__device__ __half          g_ew[(size_t)N_EDGES * 256];    // edge feats after W (host-arg only)
__device__ __half          g_h[(size_t)N_NODES * 256];     // node activations (host-arg only)
__device__ int             g_ecnt[N_EDGES];                // degrees (device-symbol only; zeroed by logits)
__device__ int             g_ncnt[N_NODES];                // (device-symbol only; zeroed by logits)
__device__ int             g_estart[N_EDGES];              // CSR offsets (device-symbol only)
__device__ int             g_nstart[N_NODES];
__device__ int             g_ecur[N_EDGES];                // scatter cursors (device-symbol only)
__device__ int             g_ncur[N_NODES];
__device__ int             g_eitems[NNZ];                  // per-edge node lists (compact CSR)
__device__ unsigned short  g_nitems[NNZ];                  // per-node edge lists (ids<20000)
__device__ float           g_logits[N_NODES];
__device__ float           g_partmax[12500];
__device__ float           g_gmax;
__device__ float           g_acc[129];                     // [0..127] sum, [128]=Z

static __device__ __forceinline__ void acc_h4(float4& acc, uint2 raw) {
    float2 f0 = __half22float2(*reinterpret_cast<__half2*>(&raw.x));
    float2 f1 = __half22float2(*reinterpret_cast<__half2*>(&raw.y));
    acc.x += f0.x; acc.y += f0.y; acc.z += f1.x; acc.w += f1.y;
}
static __device__ __forceinline__ uint2 pack_h4(float4 o) {
    __half2 v0 = __floats2half2_rn(o.x, o.y);
    __half2 v1 = __floats2half2_rn(o.z, o.w);
    uint2 pk;
    pk.x = *reinterpret_cast<unsigned*>(&v0);
    pk.y = *reinterpret_cast<unsigned*>(&v1);
    return pk;
}

// ---------------- degree histogram (cnt arrays must be 0 on entry) -------------------
__global__ void hist_kernel(const int* __restrict__ nidx, const int* __restrict__ eidx) {
    int i = blockIdx.x * blockDim.x + threadIdx.x;
    int stride = gridDim.x * blockDim.x;
    for (int j = i; j < NNZ; j += stride) {
        atomicAdd(&g_ecnt[eidx[j]], 1);
        atomicAdd(&g_ncnt[nidx[j]], 1);
    }
}

// ---------------- exclusive scan: block 0 -> edges, block 1 -> nodes -----------------
__global__ void scan_kernel() {
    const bool edges = (blockIdx.x == 0);
    int*       cnt    = edges ? g_ecnt   : g_ncnt;
    int*       start  = edges ? g_estart : g_nstart;
    int*       cursor = edges ? g_ecur   : g_ncur;
    const int  n      = edges ? N_EDGES  : N_NODES;

    __shared__ int sh[1024];
    __shared__ int s_carry;
    if (threadIdx.x == 0) s_carry = 0;
    __syncthreads();
    for (int base = 0; base < n; base += 1024) {
        int i = base + threadIdx.x;
        int v = (i < n) ? cnt[i] : 0;
        sh[threadIdx.x] = v;
        __syncthreads();
        for (int off = 1; off < 1024; off <<= 1) {
            int t = 0;
            if (threadIdx.x >= off) t = sh[threadIdx.x - off];
            __syncthreads();
            if (threadIdx.x >= off) sh[threadIdx.x] += t;
            __syncthreads();
        }
        int carry = s_carry;
        int incl = sh[threadIdx.x];
        if (i < n) {
            int excl = carry + incl - v;
            start[i] = excl;
            cursor[i] = excl;
        }
        __syncthreads();
        if (threadIdx.x == 1023) s_carry = carry + sh[1023];
        __syncthreads();
    }
}

// ---------------- CSR scatter --------------------------------------------------------
__global__ void scatter_kernel(const int* __restrict__ nidx, const int* __restrict__ eidx) {
    int i = blockIdx.x * blockDim.x + threadIdx.x;
    int stride = gridDim.x * blockDim.x;
    for (int j = i; j < NNZ; j += stride) {
        int n = nidx[j];
        int e = eidx[j];
        int p = atomicAdd(&g_ecur[e], 1);
        g_eitems[p] = n;
        int q = atomicAdd(&g_ncur[n], 1);
        g_nitems[q] = (unsigned short)e;
    }
}

// ---------------- layer-1 edge aggregation: fp32 x -> fp16 eagg ----------------------
// warp per (edge, 128-feature chunk); 8 independent float4 gathers in flight
template <int F, int CHUNKS, int LDOUT>
__global__ __launch_bounds__(256) void agg_edge_x(const float* __restrict__ src,
                                                  __half* __restrict__ dst) {
    int w = (blockIdx.x * blockDim.x + threadIdx.x) >> 5;
    int lane = threadIdx.x & 31;
    int row = w / CHUNKS;
    int ch  = w % CHUNKS;
    if (row >= N_EDGES) return;

    const int* __restrict__ lst = g_eitems + g_estart[row];
    int cnt = g_ecnt[row];

    int colbase = ch * 128 + lane * 4;
    const bool active = colbase < F;            // partial last chunk for F=300
    const float* __restrict__ sp = src + colbase;

    float4 acc = make_float4(0.f, 0.f, 0.f, 0.f);
    int i = 0;
    for (; i + 8 <= cnt; i += 8) {
        int idxreg = 0;
        if (lane < 8) idxreg = lst[i + lane];
        int ns[8];
#pragma unroll
        for (int k = 0; k < 8; k++) ns[k] = __shfl_sync(0xffffffffu, idxreg, k);
        float4 t[8];
#pragma unroll
        for (int k = 0; k < 8; k++) {
            t[k] = make_float4(0.f, 0.f, 0.f, 0.f);
            if (active) t[k] = *(const float4*)(sp + (size_t)ns[k] * F);
        }
#pragma unroll
        for (int k = 0; k < 8; k++) {
            acc.x += t[k].x; acc.y += t[k].y; acc.z += t[k].z; acc.w += t[k].w;
        }
    }
    for (; i < cnt; i++) {
        if (active) {
            float4 t = *(const float4*)(sp + (size_t)lst[i] * F);
            acc.x += t.x; acc.y += t.y; acc.z += t.z; acc.w += t.w;
        }
    }
    if (!active) return;
    float inv = (cnt > 0) ? 1.0f / (float)cnt : 0.0f;
    float4 o = make_float4(acc.x * inv, acc.y * inv, acc.z * inv, acc.w * inv);
    *(uint2*)(dst + (size_t)row * LDOUT + colbase) = pack_h4(o);
}

// ---------------- layers 2-3 edge aggregation: fp16 h -> fp16 eagg -------------------
template <int F, int CHUNKS, int LDOUT>
__global__ __launch_bounds__(256) void agg_edge_h(const __half* __restrict__ src,
                                                  __half* __restrict__ dst) {
    int w = (blockIdx.x * blockDim.x + threadIdx.x) >> 5;
    int lane = threadIdx.x & 31;
    int row = w / CHUNKS;
    int ch  = w % CHUNKS;
    if (row >= N_EDGES) return;

    const int* __restrict__ lst = g_eitems + g_estart[row];
    int cnt = g_ecnt[row];

    int colbase = ch * 128 + lane * 4;
    const __half* __restrict__ sp = src + colbase;

    float4 acc = make_float4(0.f, 0.f, 0.f, 0.f);
    int i = 0;
    for (; i + 8 <= cnt; i += 8) {
        int idxreg = 0;
        if (lane < 8) idxreg = lst[i + lane];
        int ns[8];
#pragma unroll
        for (int k = 0; k < 8; k++) ns[k] = __shfl_sync(0xffffffffu, idxreg, k);
        uint2 raw[8];
#pragma unroll
        for (int k = 0; k < 8; k++) raw[k] = *(const uint2*)(sp + (size_t)ns[k] * F);
#pragma unroll
        for (int k = 0; k < 8; k++) acc_h4(acc, raw[k]);
    }
    for (; i < cnt; i++) {
        uint2 raw = *(const uint2*)(sp + (size_t)lst[i] * F);
        acc_h4(acc, raw);
    }
    float inv = (cnt > 0) ? 1.0f / (float)cnt : 0.0f;
    float4 o = make_float4(acc.x * inv, acc.y * inv, acc.z * inv, acc.w * inv);
    *(uint2*)(dst + (size_t)row * LDOUT + colbase) = pack_h4(o);
}

// ---------------- node aggregation: fp16 ew -> fp16 h, +bias, optional lrelu ---------
template <int F, int CHUNKS, bool LRELU>
__global__ __launch_bounds__(256) void agg_node_f16(const __half* __restrict__ src,
                                                    __half* __restrict__ dst,
                                                    const float* __restrict__ bias) {
    int w = (blockIdx.x * blockDim.x + threadIdx.x) >> 5;
    int lane = threadIdx.x & 31;
    int row = w / CHUNKS;
    int ch  = w % CHUNKS;
    if (row >= N_NODES) return;

    const unsigned short* __restrict__ lst = g_nitems + g_nstart[row];
    int cnt = g_ncnt[row];

    int colbase = ch * 128 + lane * 4;
    const __half* __restrict__ sp = src + colbase;

    float4 acc = make_float4(0.f, 0.f, 0.f, 0.f);
    int i = 0;
    for (; i + 8 <= cnt; i += 8) {
        int idxreg = 0;
        if (lane < 8) idxreg = (int)lst[i + lane];
        int ns[8];
#pragma unroll
        for (int k = 0; k < 8; k++) ns[k] = __shfl_sync(0xffffffffu, idxreg, k);
        uint2 raw[8];
#pragma unroll
        for (int k = 0; k < 8; k++) raw[k] = *(const uint2*)(sp + (size_t)ns[k] * F);
#pragma unroll
        for (int k = 0; k < 8; k++) acc_h4(acc, raw[k]);
    }
    for (; i < cnt; i++) {
        uint2 raw = *(const uint2*)(sp + (size_t)lst[i] * F);
        acc_h4(acc, raw);
    }
    float inv = (cnt > 0) ? 1.0f / (float)cnt : 0.0f;
    float4 bb = *(const float4*)(bias + colbase);
    float4 o;
    o.x = acc.x * inv + bb.x;
    o.y = acc.y * inv + bb.y;
    o.z = acc.z * inv + bb.z;
    o.w = acc.w * inv + bb.w;
    if (LRELU) {
        o.x = (o.x > 0.f) ? o.x : 0.01f * o.x;
        o.y = (o.y > 0.f) ? o.y : 0.01f * o.y;
        o.z = (o.z > 0.f) ? o.z : 0.01f * o.z;
        o.w = (o.w > 0.f) ? o.w : 0.01f * o.w;
    }
    *(uint2*)(dst + (size_t)row * F + colbase) = pack_h4(o);
}

// ---------------- SGEMM: fp16 A (lda-padded), fp32 B, fp16 C, fp32 accum -------------
// BM=128, BN=64, BK=16, 256 threads, 8x4 per thread.
// A pad columns (K..lda) are never written -> zero from static init -> safe to read.
__global__ __launch_bounds__(256) void sgemm_kernel(const __half* __restrict__ A,
                                                    const float* __restrict__ B,
                                                    __half* __restrict__ C,
                                                    int M, int K, int N, int lda) {
    __shared__ float As[16][136];
    __shared__ float Bs[16][64];
    const int tid = threadIdx.x;
    const int bm = blockIdx.x * 128;
    const int bn = blockIdx.y * 64;
    const int a_row = tid >> 1;            // 0..127
    const int a_grp = (tid & 1) * 8;       // 0 or 8 (halfs)
    const int b_row = tid >> 4;            // 0..15
    const int b_col = (tid & 15) * 4;      // 0..60
    const int ty = tid >> 4;               // rows ty*8
    const int tx = tid & 15;               // cols tx*4
    float acc[8][4];
#pragma unroll
    for (int i = 0; i < 8; i++)
#pragma unroll
        for (int j = 0; j < 4; j++) acc[i][j] = 0.f;

    const bool arow_ok = (bm + a_row) < M;
    const __half* Ab = A + (size_t)(bm + a_row) * lda;

    for (int kt = 0; kt < K; kt += 16) {
        {   // A: 8 halfs per thread (16B aligned thanks to lda padding)
            uint4 raw = make_uint4(0u, 0u, 0u, 0u);
            if (arow_ok) raw = *(const uint4*)(Ab + kt + a_grp);
            const __half2* hp = reinterpret_cast<const __half2*>(&raw);
#pragma unroll
            for (int j = 0; j < 4; j++) {
                float2 f = __half22float2(hp[j]);
                As[a_grp + j * 2 + 0][a_row] = f.x;
                As[a_grp + j * 2 + 1][a_row] = f.y;
            }
        }
        {   // B: 4 floats per thread
            int k = kt + b_row;
            float4 bv = make_float4(0.f, 0.f, 0.f, 0.f);
            if (k < K) bv = *(const float4*)(B + (size_t)k * N + bn + b_col);
            *(float4*)&Bs[b_row][b_col] = bv;
        }
        __syncthreads();
#pragma unroll
        for (int k = 0; k < 16; k++) {
            float4 a0 = *(const float4*)&As[k][ty * 8];
            float4 a1 = *(const float4*)&As[k][ty * 8 + 4];
            float4 bv = *(const float4*)&Bs[k][tx * 4];
            float a[8] = {a0.x, a0.y, a0.z, a0.w, a1.x, a1.y, a1.z, a1.w};
            float b[4] = {bv.x, bv.y, bv.z, bv.w};
#pragma unroll
            for (int i = 0; i < 8; i++)
#pragma unroll
                for (int j = 0; j < 4; j++) acc[i][j] += a[i] * b[j];
        }
        __syncthreads();
    }
#pragma unroll
    for (int i = 0; i < 8; i++) {
        int r = bm + ty * 8 + i;
        if (r < M) {
            float4 o = make_float4(acc[i][0], acc[i][1], acc[i][2], acc[i][3]);
            *(uint2*)(C + (size_t)r * N + bn + tx * 4) = pack_h4(o);
        }
    }
}

// ---------------- attention epilogue (h fp16, stride 128) ----------------------------
// Also zeroes the degree arrays for the next replay.
__global__ void logits_kernel(const __half* __restrict__ h,
                              const float* __restrict__ aw, const float* __restrict__ ab) {
    __shared__ float smax[8];
    int gidx = blockIdx.x * blockDim.x + threadIdx.x;
    int gstride = gridDim.x * blockDim.x;
    for (int j = gidx; j < N_EDGES; j += gstride) g_ecnt[j] = 0;
    for (int j = gidx; j < N_NODES; j += gstride) g_ncnt[j] = 0;

    int w = gidx >> 5;
    int lane = threadIdx.x & 31;
    float lg = -1e30f;
    if (w < N_NODES) {
        uint2 raw = *(const uint2*)(h + (size_t)w * 128 + lane * 4);
        float2 f0 = __half22float2(*reinterpret_cast<__half2*>(&raw.x));
        float2 f1 = __half22float2(*reinterpret_cast<__half2*>(&raw.y));
        float4 wv = ((const float4*)aw)[lane];
        float d = f0.x * wv.x + f0.y * wv.y + f1.x * wv.z + f1.y * wv.w;
#pragma unroll
        for (int off = 16; off > 0; off >>= 1) d += __shfl_xor_sync(0xffffffffu, d, off);
        d += ab[0];
        if (lane == 0) g_logits[w] = d;
        lg = d;
    }
    int wl = threadIdx.x >> 5;
    if (lane == 0) smax[wl] = lg;
    __syncthreads();
    if (threadIdx.x == 0) {
        float m = smax[0];
#pragma unroll
        for (int j = 1; j < 8; j++) m = fmaxf(m, smax[j]);
        g_partmax[blockIdx.x] = m;
    }
}

__global__ void maxred_kernel(int nparts) {
    __shared__ float sm[32];
    if (threadIdx.x < 129) g_acc[threadIdx.x] = 0.0f;
    float m = -1e30f;
    for (int i = threadIdx.x; i < nparts; i += 1024) m = fmaxf(m, g_partmax[i]);
#pragma unroll
    for (int off = 16; off > 0; off >>= 1) m = fmaxf(m, __shfl_xor_sync(0xffffffffu, m, off));
    if ((threadIdx.x & 31) == 0) sm[threadIdx.x >> 5] = m;
    __syncthreads();
    if (threadIdx.x < 32) {
        float v = sm[threadIdx.x];
#pragma unroll
        for (int off = 16; off > 0; off >>= 1) v = fmaxf(v, __shfl_xor_sync(0xffffffffu, v, off));
        if (threadIdx.x == 0) g_gmax = v;
    }
}

__global__ void accum_kernel(const __half* __restrict__ h) {
    int t = threadIdx.x;
    float gmax = g_gmax;
    int per = (N_NODES + gridDim.x - 1) / gridDim.x;
    int n0 = blockIdx.x * per;
    int n1 = n0 + per;
    if (n1 > N_NODES) n1 = N_NODES;
    float acc = 0.f, z = 0.f;
    for (int n = n0; n < n1; n++) {
        float wgt = expf(g_logits[n] - gmax);
        acc += wgt * __half2float(h[(size_t)n * 128 + t]);
        z += wgt;
    }
    atomicAdd(&g_acc[t], acc);
    if (t == 0) atomicAdd(&g_acc[128], z);
}

__global__ void finalize_kernel(float* __restrict__ out) {
    int t = threadIdx.x;
    out[t] = g_acc[t] / g_acc[128];
}

// ---------------- launch -------------------------------------------------------------
extern "C" void kernel_launch(void* const* d_in, const int* in_sizes, int n_in,
                              void* d_out, int out_size) {
    const float* x       = (const float*)d_in[0];          // [100000, 300]
    const int*   nidx    = (const int*)d_in[1];
    const int*   eidx    = ((const int*)d_in[1]) + NNZ;
    const float* W1      = (const float*)d_in[2];          // [300,256]
    const float* b1      = (const float*)d_in[3];
    const float* W2      = (const float*)d_in[4];          // [256,256]
    const float* b2      = (const float*)d_in[5];
    const float* W3      = (const float*)d_in[6];          // [256,128]
    const float* b3      = (const float*)d_in[7];
    const float* attn_W  = (const float*)d_in[8];          // [128,1]
    const float* attn_b  = (const float*)d_in[9];          // [1]
    float* out = (float*)d_out;                            // [128]

    // compact CSR build (cnt arrays zero at entry: static init / logits epilogue)
    hist_kernel<<<2048, 256>>>(nidx, eidx);
    scan_kernel<<<2, 1024>>>();
    scatter_kernel<<<2048, 256>>>(nidx, eidx);

    // Layer 1 (slot 4 = agg_edge_x for ncu capture)
    agg_edge_x<300, 3, LDA1><<<7500, 256>>>(x, g_eagg);
    sgemm_kernel<<<dim3(157, 4), 256>>>(g_eagg, W1, g_ew, N_EDGES, 300, 256, LDA1);
    agg_node_f16<256, 2, true><<<25000, 256>>>(g_ew, g_h, b1);

    // Layer 2
    agg_edge_h<256, 2, 256><<<5000, 256>>>(g_h, g_eagg);
    sgemm_kernel<<<dim3(157, 4), 256>>>(g_eagg, W2, g_ew, N_EDGES, 256, 256, 256);
    agg_node_f16<256, 2, true><<<25000, 256>>>(g_ew, g_h, b2);

    // Layer 3 (no activation)
    agg_edge_h<256, 2, 256><<<5000, 256>>>(g_h, g_eagg);
    sgemm_kernel<<<dim3(157, 2), 256>>>(g_eagg, W3, g_ew, N_EDGES, 256, 128, 256);
    agg_node_f16<128, 1, false><<<12500, 256>>>(g_ew, g_h, b3);

    // Attention pooling
    logits_kernel<<<12500, 256>>>(g_h, attn_W, attn_b);
    maxred_kernel<<<1, 1024>>>(12500);
    accum_kernel<<<512, 128>>>(g_h);
    finalize_kernel<<<1, 128>>>(out);
}